// round 1
// baseline (speedup 1.0000x reference)
#include <cuda_runtime.h>
#include <math.h>
#include <stdint.h>

// Problem constants
#define Bq 256
#define Tt 64
#define Ee 300
#define Hh 512
#define H2 1024
#define H4 2048
#define DAa 350
#define Rr 16
#define Ss 64
#define Aa 16
#define NRr 3

// ---------------- scratch (device globals; no allocation allowed) ----------
__device__ float g_x[Tt * Bq * Ee];            // embedded input, (t,b,e)
__device__ float g_pre_f[Tt * Bq * H4];        // input projection fwd (reused per layer)
__device__ float g_pre_b[Tt * Bq * H4];        // input projection bwd
__device__ float g_l0[Tt * Bq * H2];           // layer0 output (t,b,2H)
__device__ float g_l1[Tt * Bq * H2];           // layer1 output (t,b,2H)
__device__ float g_hf[Bq * Hh], g_cf[Bq * Hh];
__device__ float g_hb[Bq * Hh], g_cb[Bq * Hh];
__device__ float g_zf[Bq * H4], g_zb[Bq * H4];
__device__ float g_hbar[Tt * Bq * DAa];        // (t,b,a)
__device__ float g_alphas[Tt * Bq * Rr];       // (t,b,r)
__device__ float g_votes[Bq * Rr * Ss * Aa];   // (b,r,s*a)

__device__ __forceinline__ float sigf(float x) { return 1.0f / (1.0f + expf(-x)); }

// ---------------- embedding lookup: x[t][b][e] = emb[tokens[b][t]][e] ------
__global__ void embed_kernel(const int* __restrict__ tokens,
                             const float* __restrict__ emb) {
    size_t n = (size_t)Tt * Bq * Ee;
    for (size_t i = (size_t)blockIdx.x * blockDim.x + threadIdx.x; i < n;
         i += (size_t)gridDim.x * blockDim.x) {
        int e = (int)(i % Ee);
        size_t tb = i / Ee;
        int b = (int)(tb % Bq);
        int t = (int)(tb / Bq);
        int tok = tokens[b * Tt + t];
        g_x[i] = emb[(size_t)tok * Ee + e];
    }
}

// ---------------- generic NT SGEMM: C[M,N] = A[M,K] * B[N,K]^T -------------
// optional act==1 -> tanh on output. 64x64x16 tiles, 16x16 threads, 4x4/thread.
__global__ void gemm_nt(const float* __restrict__ A, const float* __restrict__ Bm,
                        float* __restrict__ C, int M, int N, int K, int act) {
    __shared__ float As[16][64];
    __shared__ float Bs[16][64];
    int m0 = blockIdx.y * 64, n0 = blockIdx.x * 64;
    int tid = threadIdx.y * 16 + threadIdx.x;
    float acc[4][4] = {};
    for (int k0 = 0; k0 < K; k0 += 16) {
#pragma unroll
        for (int q = 0; q < 4; q++) {
            int e = tid + q * 256;
            int r = e >> 4, c = e & 15;
            int kk = k0 + c;
            int mm = m0 + r;
            As[c][r] = (mm < M && kk < K) ? A[(size_t)mm * K + kk] : 0.0f;
            int nn = n0 + r;
            Bs[c][r] = (nn < N && kk < K) ? Bm[(size_t)nn * K + kk] : 0.0f;
        }
        __syncthreads();
#pragma unroll
        for (int k = 0; k < 16; k++) {
            float a[4], b[4];
#pragma unroll
            for (int i = 0; i < 4; i++) a[i] = As[k][threadIdx.y * 4 + i];
#pragma unroll
            for (int j = 0; j < 4; j++) b[j] = Bs[k][threadIdx.x * 4 + j];
#pragma unroll
            for (int i = 0; i < 4; i++)
#pragma unroll
                for (int j = 0; j < 4; j++) acc[i][j] += a[i] * b[j];
        }
        __syncthreads();
    }
#pragma unroll
    for (int i = 0; i < 4; i++)
#pragma unroll
        for (int j = 0; j < 4; j++) {
            int mm = m0 + threadIdx.y * 4 + i;
            int nn = n0 + threadIdx.x * 4 + j;
            if (mm < M && nn < N) {
                float v = acc[i][j];
                if (act) v = tanhf(v);
                C[(size_t)mm * N + nn] = v;
            }
        }
}

// ---------------- recurrence GEMM: z = h @ Whh^T, both dirs in one launch --
// fixed M=256, N=2048, K=512. blockIdx.z selects direction.
__global__ void recur_gemm(const float* __restrict__ hf, const float* __restrict__ hb,
                           const float* __restrict__ Wf, const float* __restrict__ Wb,
                           float* __restrict__ zf_, float* __restrict__ zb_) {
    const float* A = blockIdx.z ? hb : hf;
    const float* W = blockIdx.z ? Wb : Wf;
    float* Z = blockIdx.z ? zb_ : zf_;
    __shared__ float As[16][64];
    __shared__ float Ws[16][64];
    int m0 = blockIdx.y * 64, n0 = blockIdx.x * 64;
    int tid = threadIdx.y * 16 + threadIdx.x;
    float acc[4][4] = {};
    for (int k0 = 0; k0 < Hh; k0 += 16) {
#pragma unroll
        for (int q = 0; q < 4; q++) {
            int e = tid + q * 256;
            int r = e >> 4, c = e & 15;
            As[c][r] = A[(m0 + r) * Hh + k0 + c];
            Ws[c][r] = W[(n0 + r) * Hh + k0 + c];
        }
        __syncthreads();
#pragma unroll
        for (int k = 0; k < 16; k++) {
            float a[4], w[4];
#pragma unroll
            for (int i = 0; i < 4; i++) a[i] = As[k][threadIdx.y * 4 + i];
#pragma unroll
            for (int j = 0; j < 4; j++) w[j] = Ws[k][threadIdx.x * 4 + j];
#pragma unroll
            for (int i = 0; i < 4; i++)
#pragma unroll
                for (int j = 0; j < 4; j++) acc[i][j] += a[i] * w[j];
        }
        __syncthreads();
    }
#pragma unroll
    for (int i = 0; i < 4; i++)
#pragma unroll
        for (int j = 0; j < 4; j++)
            Z[(m0 + threadIdx.y * 4 + i) * H4 + n0 + threadIdx.x * 4 + j] = acc[i][j];
}

// ---------------- LSTM gates: c,h update + write into layer output --------
__global__ void gate_kernel(int step,
                            const float* __restrict__ pre_f, const float* __restrict__ pre_b,
                            const float* __restrict__ bias_f, const float* __restrict__ bias_b,
                            float* __restrict__ out) {
    int dir = blockIdx.z;
    int idx = blockIdx.x * blockDim.x + threadIdx.x;
    if (idx >= Bq * Hh) return;
    int b = idx / Hh, h = idx % Hh;
    int tc = dir ? (Tt - 1 - step) : step;
    const float* z = dir ? g_zb : g_zf;
    const float* pre = dir ? pre_b : pre_f;
    const float* bias = dir ? bias_b : bias_f;
    float* cs = dir ? g_cb : g_cf;
    float* hs = dir ? g_hb : g_hf;
    size_t prow = (size_t)(tc * Bq + b) * H4;
    int zrow = b * H4;
    float zi = z[zrow + h]          + pre[prow + h]          + bias[h];
    float zf = z[zrow + Hh + h]     + pre[prow + Hh + h]     + bias[Hh + h];
    float zg = z[zrow + 2 * Hh + h] + pre[prow + 2 * Hh + h] + bias[2 * Hh + h];
    float zo = z[zrow + 3 * Hh + h] + pre[prow + 3 * Hh + h] + bias[3 * Hh + h];
    float c = cs[idx];
    c = sigf(zf) * c + sigf(zi) * tanhf(zg);
    float hn = sigf(zo) * tanhf(c);
    cs[idx] = c;
    hs[idx] = hn;
    out[(size_t)(tc * Bq + b) * H2 + dir * Hh + h] = hn;
}

// ---------------- zero LSTM states -----------------------------------------
__global__ void zero_states_kernel() {
    int i = blockIdx.x * blockDim.x + threadIdx.x;
    if (i < Bq * Hh) {
        g_hf[i] = 0.0f; g_cf[i] = 0.0f;
        g_hb[i] = 0.0f; g_cb[i] = 0.0f;
    }
}

// ---------------- sent: sent[b,r,e] = sum_t alphas[t,b,r] * l1[t,b,e] -------
__global__ void sent_kernel(const float* __restrict__ alphas,
                            const float* __restrict__ l1,
                            float* __restrict__ outSent) {
    int b = blockIdx.x;
    __shared__ float al[Tt * Rr];
    int tid = threadIdx.x;
    for (int i = tid; i < Tt * Rr; i += 256) {
        int t = i / Rr, r = i % Rr;
        al[i] = alphas[(size_t)(t * Bq + b) * Rr + r];
    }
    __syncthreads();
    for (int e = tid; e < H2; e += 256) {
        float acc[Rr];
#pragma unroll
        for (int r = 0; r < Rr; r++) acc[r] = 0.0f;
        for (int t = 0; t < Tt; t++) {
            float v = l1[(size_t)(t * Bq + b) * H2 + e];
#pragma unroll
            for (int r = 0; r < Rr; r++) acc[r] += al[t * Rr + r] * v;
        }
#pragma unroll
        for (int r = 0; r < Rr; r++)
            outSent[(size_t)(b * Rr + r) * H2 + e] = acc[r];
    }
}

// ---------------- votes: votes[b,r,o] = sum_i sent[b,r,i] * capsW[r,i,o] ----
// NN GEMM per r (blockIdx.z): M=256, N=1024, K=1024
__global__ void votes_gemm(const float* __restrict__ sent,
                           const float* __restrict__ capsW,
                           float* __restrict__ votes) {
    int rr = blockIdx.z;
    const float* Bp = capsW + (size_t)rr * H2 * (Ss * Aa);
    __shared__ float As[16][64];
    __shared__ float Bs[16][65];
    int m0 = blockIdx.y * 64, n0 = blockIdx.x * 64;
    int tid = threadIdx.y * 16 + threadIdx.x;
    float acc[4][4] = {};
    for (int k0 = 0; k0 < H2; k0 += 16) {
#pragma unroll
        for (int q = 0; q < 4; q++) {
            int e = tid + q * 256;
            int r = e >> 4, c = e & 15;
            As[c][r] = sent[((size_t)(m0 + r) * Rr + rr) * H2 + k0 + c];
            int kr = e >> 6, nc = e & 63;
            Bs[kr][nc] = Bp[(size_t)(k0 + kr) * (Ss * Aa) + n0 + nc];
        }
        __syncthreads();
#pragma unroll
        for (int k = 0; k < 16; k++) {
            float a[4], w[4];
#pragma unroll
            for (int i = 0; i < 4; i++) a[i] = As[k][threadIdx.y * 4 + i];
#pragma unroll
            for (int j = 0; j < 4; j++) w[j] = Bs[k][threadIdx.x * 4 + j];
#pragma unroll
            for (int i = 0; i < 4; i++)
#pragma unroll
                for (int j = 0; j < 4; j++) acc[i][j] += a[i] * w[j];
        }
        __syncthreads();
    }
#pragma unroll
    for (int i = 0; i < 4; i++)
#pragma unroll
        for (int j = 0; j < 4; j++) {
            int mm = m0 + threadIdx.y * 4 + i;
            int nn = n0 + threadIdx.x * 4 + j;
            votes[((size_t)mm * Rr + rr) * (Ss * Aa) + nn] = acc[i][j];
        }
}

// ---------------- dynamic routing (NR=3) + class logits ---------------------
__global__ void routing_kernel(const float* __restrict__ votes,
                               float* __restrict__ outCls) {
    int b = blockIdx.x, tid = threadIdx.x;
    __shared__ float logits[Rr * Ss];
    __shared__ float route[Rr * Ss];
    __shared__ float pre[Ss * Aa];
    __shared__ float scale[Ss];
    for (int i = tid; i < Rr * Ss; i += 256) logits[i] = 0.0f;
    const float* vb = votes + (size_t)b * Rr * Ss * Aa;
    for (int it = 0; it < NRr; it++) {
        __syncthreads();
        // softmax over s for each r (16 rows of 64)
        if (tid < Rr) {
            float mx = -1e30f;
            for (int s = 0; s < Ss; s++) mx = fmaxf(mx, logits[tid * Ss + s]);
            float sum = 0.0f;
            for (int s = 0; s < Ss; s++) {
                float e = expf(logits[tid * Ss + s] - mx);
                route[tid * Ss + s] = e;
                sum += e;
            }
            float inv = 1.0f / sum;
            for (int s = 0; s < Ss; s++) route[tid * Ss + s] *= inv;
        }
        __syncthreads();
        // preact[s,a] = sum_r route[r,s] * votes[b,r,s,a]
        for (int i = tid; i < Ss * Aa; i += 256) {
            int s = i / Aa, a = i % Aa;
            float acc = 0.0f;
            for (int r = 0; r < Rr; r++)
                acc += route[r * Ss + s] * vb[(r * Ss + s) * Aa + a];
            pre[i] = acc;
        }
        __syncthreads();
        // squash scale per s; final iter writes class logits = n2/(0.5+n2)
        if (tid < Ss) {
            float n2 = 0.0f;
            for (int a = 0; a < Aa; a++) n2 += pre[tid * Aa + a] * pre[tid * Aa + a];
            float n = sqrtf(n2);
            scale[tid] = n / (0.5f + n2);
            if (it == NRr - 1) outCls[b * Ss + tid] = n2 / (0.5f + n2);
        }
        __syncthreads();
        // logits += votes . act  (act = pre * scale); skip on last iteration
        if (it < NRr - 1) {
            for (int i = tid; i < Rr * Ss; i += 256) {
                int r = i / Ss, s = i % Ss;
                float acc = 0.0f;
                float sc = scale[s];
                for (int a = 0; a < Aa; a++)
                    acc += vb[(r * Ss + s) * Aa + a] * pre[s * Aa + a] * sc;
                logits[i] += acc;
            }
        }
    }
}

// ---------------- host launch ------------------------------------------------
static float* symf(const void* s) {
    void* p = nullptr;
    cudaGetSymbolAddress(&p, s);
    return (float*)p;
}

extern "C" void kernel_launch(void* const* d_in, const int* in_sizes, int n_in,
                              void* d_out, int out_size) {
    const int*   tokens  = (const int*)d_in[0];
    const float* emb     = (const float*)d_in[2];
    const float* Wih_l0f = (const float*)d_in[3];
    const float* Whh_l0f = (const float*)d_in[4];
    const float* b_l0f   = (const float*)d_in[5];
    const float* Wih_l0b = (const float*)d_in[6];
    const float* Whh_l0b = (const float*)d_in[7];
    const float* b_l0b   = (const float*)d_in[8];
    const float* Wih_l1f = (const float*)d_in[9];
    const float* Whh_l1f = (const float*)d_in[10];
    const float* b_l1f   = (const float*)d_in[11];
    const float* Wih_l1b = (const float*)d_in[12];
    const float* Whh_l1b = (const float*)d_in[13];
    const float* b_l1b   = (const float*)d_in[14];
    const float* ws1     = (const float*)d_in[15];
    const float* ws2     = (const float*)d_in[16];
    const float* capsW   = (const float*)d_in[17];
    float* out = (float*)d_out;

    float* x     = symf(g_x);
    float* pre_f = symf(g_pre_f);
    float* pre_b = symf(g_pre_b);
    float* l0    = symf(g_l0);
    float* l1    = symf(g_l1);
    float* hf    = symf(g_hf);
    float* hb    = symf(g_hb);
    float* zf    = symf(g_zf);
    float* zb    = symf(g_zb);
    float* hbar  = symf(g_hbar);
    float* alph  = symf(g_alphas);
    float* votes = symf(g_votes);

    dim3 thr(16, 16);
    const int MB = Tt * Bq;  // 16384

    // 1. embedding
    embed_kernel<<<4096, 256>>>(tokens, emb);

    // 2. layer0 input projections (x @ Wih^T)
    {
        dim3 grid(H4 / 64, MB / 64);
        gemm_nt<<<grid, thr>>>(x, Wih_l0f, pre_f, MB, H4, Ee, 0);
        gemm_nt<<<grid, thr>>>(x, Wih_l0b, pre_b, MB, H4, Ee, 0);
    }
    // 3. layer0 recurrence
    zero_states_kernel<<<(Bq * Hh + 255) / 256, 256>>>();
    for (int t = 0; t < Tt; t++) {
        recur_gemm<<<dim3(H4 / 64, Bq / 64, 2), thr>>>(hf, hb, Whh_l0f, Whh_l0b, zf, zb);
        gate_kernel<<<dim3((Bq * Hh + 255) / 256, 1, 2), 256>>>(t, pre_f, pre_b, b_l0f, b_l0b, l0);
    }

    // 4. layer1 input projections (l0 @ Wih^T)
    {
        dim3 grid(H4 / 64, MB / 64);
        gemm_nt<<<grid, thr>>>(l0, Wih_l1f, pre_f, MB, H4, H2, 0);
        gemm_nt<<<grid, thr>>>(l0, Wih_l1b, pre_b, MB, H4, H2, 0);
    }
    // 5. layer1 recurrence
    zero_states_kernel<<<(Bq * Hh + 255) / 256, 256>>>();
    for (int t = 0; t < Tt; t++) {
        recur_gemm<<<dim3(H4 / 64, Bq / 64, 2), thr>>>(hf, hb, Whh_l1f, Whh_l1b, zf, zb);
        gate_kernel<<<dim3((Bq * Hh + 255) / 256, 1, 2), 256>>>(t, pre_f, pre_b, b_l1f, b_l1b, l1);
    }

    // 6. attention: hbar = tanh(l1 @ ws1^T), alphas = hbar @ ws2^T
    gemm_nt<<<dim3((DAa + 63) / 64, MB / 64), thr>>>(l1, ws1, hbar, MB, DAa, H2, 1);
    gemm_nt<<<dim3(1, MB / 64), thr>>>(hbar, ws2, alph, MB, Rr, DAa, 0);

    // 7. sent -> written directly into d_out[0 : B*R*2H)
    sent_kernel<<<Bq, 256>>>(alph, l1, out);

    // 8. votes (per-r NN GEMM reading sent from d_out)
    votes_gemm<<<dim3((Ss * Aa) / 64, Bq / 64, Rr), thr>>>(out, capsW, votes);

    // 9. dynamic routing -> class_logits at d_out[B*R*2H : B*R*2H + B*S)
    routing_kernel<<<Bq, 256>>>(votes, out + (size_t)Bq * Rr * H2);
}

// round 3
// speedup vs baseline: 2.0433x; 2.0433x over previous
#include <cuda_runtime.h>
#include <math.h>
#include <stdint.h>

typedef unsigned long long ull;

// Problem constants
#define Bq 256
#define Tt 64
#define Ee 300
#define EeP 304
#define Hh 512
#define H2 1024
#define H4 2048
#define DAa 350
#define Rr 16
#define Ss 64
#define Aa 16
#define NRr 3

// ---------------- scratch (device globals) ----------------------------------
__device__ float g_x[Tt * Bq * EeP];           // embedded input, padded K
__device__ float g_pre_f[Tt * Bq * H4];        // input projection fwd (permuted cols)
__device__ float g_pre_b[Tt * Bq * H4];
__device__ float g_l0[Tt * Bq * H2];
__device__ float g_l1[Tt * Bq * H2];
__device__ float g_hf2[2][Bq * Hh];
__device__ float g_hb2[2][Bq * Hh];
__device__ float g_cf[Bq * Hh], g_cb[Bq * Hh];
__device__ float g_hbar[Tt * Bq * DAa];
__device__ float g_alphas[Tt * Bq * Rr];
__device__ float g_votes[Bq * Rr * Ss * Aa];
// packed weights: row = h*4+g
__device__ float g_wih0f[H4 * EeP], g_wih0b[H4 * EeP];
__device__ float g_wih1f[H4 * H2],  g_wih1b[H4 * H2];
__device__ float g_whh0f[H4 * Hh],  g_whh0b[H4 * Hh];
__device__ float g_whh1f[H4 * Hh],  g_whh1b[H4 * Hh];
__device__ float g_b0f[H4], g_b0b[H4], g_b1f[H4], g_b1b[H4];

__device__ __forceinline__ float sigf(float x) { return 1.0f / (1.0f + expf(-x)); }

__device__ __forceinline__ ull pack2(float lo, float hi) {
    ull r; asm("mov.b64 %0, {%1,%2};" : "=l"(r) : "f"(lo), "f"(hi)); return r;
}
__device__ __forceinline__ void unpack2(ull v, float& lo, float& hi) {
    asm("mov.b64 {%0,%1}, %2;" : "=f"(lo), "=f"(hi) : "l"(v));
}
__device__ __forceinline__ ull ffma2(ull a, ull b, ull c) {
    ull d; asm("fma.rn.f32x2 %0, %1, %2, %3;" : "=l"(d) : "l"(a), "l"(b), "l"(c)); return d;
}

// ---------------- embedding lookup, padded to EeP ---------------------------
__global__ void embed_kernel(const int* __restrict__ tokens,
                             const float* __restrict__ emb) {
    size_t n = (size_t)Tt * Bq * EeP;
    for (size_t i = (size_t)blockIdx.x * blockDim.x + threadIdx.x; i < n;
         i += (size_t)gridDim.x * blockDim.x) {
        int e = (int)(i % EeP);
        size_t tb = i / EeP;
        int b = (int)(tb % Bq);
        int t = (int)(tb / Bq);
        if (e < Ee) {
            int tok = tokens[b * Tt + t];
            g_x[i] = emb[(size_t)tok * Ee + e];
        } else {
            g_x[i] = 0.0f;
        }
    }
}

// ---------------- weight repack: Wp[h*4+g][k] = W[g*H+h][k], pad K->Kp ------
__global__ void pack_w(const float* __restrict__ W, float* __restrict__ Wp,
                       int K, int Kp) {
    int total = H4 * Kp;
    for (int idx = blockIdx.x * blockDim.x + threadIdx.x; idx < total;
         idx += gridDim.x * blockDim.x) {
        int r = idx / Kp, k = idx - r * Kp;
        int h = r >> 2, g = r & 3;
        Wp[idx] = (k < K) ? W[(size_t)(g * Hh + h) * K + k] : 0.0f;
    }
}
__global__ void pack_bias(const float* __restrict__ b, float* __restrict__ bp) {
    int idx = blockIdx.x * blockDim.x + threadIdx.x;
    if (idx < H4) {
        int h = idx >> 2, g = idx & 3;
        bp[idx] = b[g * Hh + h];
    }
}

// ---------------- big GEMM: C[M,N] = A[M,K] @ B[N,K]^T, K%16==0 -------------
// 128x128 tile, 256 threads, 8x8/thread, f32x2 packed FMA, reg double-buffer.
__global__ __launch_bounds__(256)
void gemm128(const float* __restrict__ A, const float* __restrict__ Bm,
             float* __restrict__ C, int M, int N, int K, int act) {
    __shared__ __align__(16) float As[16][132];
    __shared__ __align__(16) float Bs[16][132];
    const int tid = threadIdx.x;
    const int tx = tid & 15, ty = tid >> 4;
    const int m0 = blockIdx.y * 128, n0 = blockIdx.x * 128;
    const int lr = tid >> 2;
    const int lk = (tid & 3) << 2;

    ull acc[8][4];
#pragma unroll
    for (int i = 0; i < 8; i++)
#pragma unroll
        for (int j = 0; j < 4; j++) acc[i][j] = 0ULL;

    const int ma = m0 + lr, mb = m0 + lr + 64;
    const int na = n0 + lr, nb = n0 + lr + 64;
    const float4 z4 = make_float4(0.f, 0.f, 0.f, 0.f);

    float4 pa0 = (ma < M) ? *(const float4*)&A[(size_t)ma * K + lk] : z4;
    float4 pa1 = (mb < M) ? *(const float4*)&A[(size_t)mb * K + lk] : z4;
    float4 pb0 = (na < N) ? *(const float4*)&Bm[(size_t)na * K + lk] : z4;
    float4 pb1 = (nb < N) ? *(const float4*)&Bm[(size_t)nb * K + lk] : z4;

    for (int k0 = 0; k0 < K; k0 += 16) {
        __syncthreads();
        As[lk + 0][lr] = pa0.x; As[lk + 1][lr] = pa0.y;
        As[lk + 2][lr] = pa0.z; As[lk + 3][lr] = pa0.w;
        As[lk + 0][lr + 64] = pa1.x; As[lk + 1][lr + 64] = pa1.y;
        As[lk + 2][lr + 64] = pa1.z; As[lk + 3][lr + 64] = pa1.w;
        Bs[lk + 0][lr] = pb0.x; Bs[lk + 1][lr] = pb0.y;
        Bs[lk + 2][lr] = pb0.z; Bs[lk + 3][lr] = pb0.w;
        Bs[lk + 0][lr + 64] = pb1.x; Bs[lk + 1][lr + 64] = pb1.y;
        Bs[lk + 2][lr + 64] = pb1.z; Bs[lk + 3][lr + 64] = pb1.w;
        __syncthreads();
        int k1 = k0 + 16;
        if (k1 < K) {
            pa0 = (ma < M) ? *(const float4*)&A[(size_t)ma * K + k1 + lk] : z4;
            pa1 = (mb < M) ? *(const float4*)&A[(size_t)mb * K + k1 + lk] : z4;
            pb0 = (na < N) ? *(const float4*)&Bm[(size_t)na * K + k1 + lk] : z4;
            pb1 = (nb < N) ? *(const float4*)&Bm[(size_t)nb * K + k1 + lk] : z4;
        }
#pragma unroll
        for (int k = 0; k < 16; k++) {
            ull b2[4];
            const ull* bp = (const ull*)&Bs[k][tx << 3];
            b2[0] = bp[0]; b2[1] = bp[1]; b2[2] = bp[2]; b2[3] = bp[3];
#pragma unroll
            for (int i = 0; i < 8; i++) {
                float a = As[k][(ty << 3) + i];
                ull ad = pack2(a, a);
#pragma unroll
                for (int j = 0; j < 4; j++) acc[i][j] = ffma2(ad, b2[j], acc[i][j]);
            }
        }
    }
#pragma unroll
    for (int i = 0; i < 8; i++) {
        int m = m0 + (ty << 3) + i;
        if (m >= M) continue;
#pragma unroll
        for (int j = 0; j < 4; j++) {
            float lo, hi;
            unpack2(acc[i][j], lo, hi);
            if (act) { lo = tanhf(lo); hi = tanhf(hi); }
            int n = n0 + (tx << 3) + 2 * j;
            if (n < N) C[(size_t)m * N + n] = lo;
            if (n + 1 < N) C[(size_t)m * N + n + 1] = hi;
        }
    }
}

// ---------------- fused LSTM recurrence step ---------------------------------
// z = h_in @ Wp^T (+pre +bias) -> gates -> c,h update -> layer output.
// Wp row r=4h+g. Block: 64 batch x 32 h (=128 permuted cols). dirs via blockIdx.z.
__global__ __launch_bounds__(256)
void recur_fused(int step,
                 const float* __restrict__ Wpf, const float* __restrict__ Wpb,
                 const float* __restrict__ bpf, const float* __restrict__ bpb,
                 const float* __restrict__ pre_f, const float* __restrict__ pre_b,
                 const float* __restrict__ hinf, const float* __restrict__ hinb,
                 float* __restrict__ houtf, float* __restrict__ houtb,
                 float* __restrict__ out) {
    const int tid = threadIdx.x;
    const int tx = tid & 31, ty = tid >> 5;
    const int h0 = blockIdx.x * 32;
    const int b0 = blockIdx.y * 64;
    const int dir = blockIdx.z;
    const float* W   = dir ? Wpb : Wpf;
    const float* bia = dir ? bpb : bpf;
    const float* pre = dir ? pre_b : pre_f;
    const float* hin = dir ? hinb : hinf;
    float* hout = dir ? houtb : houtf;
    float* cs   = dir ? g_cb : g_cf;
    const int tc = dir ? (Tt - 1 - step) : step;

    __shared__ __align__(16) float Hs[16][68];
    __shared__ __align__(16) float Ws[16][132];

    ull acc[8][2];
#pragma unroll
    for (int i = 0; i < 8; i++) { acc[i][0] = 0ULL; acc[i][1] = 0ULL; }

    const float* Wbase = W + (size_t)(4 * h0) * Hh;
    const int lr = tid >> 2;           // 0..63
    const int lk = (tid & 3) << 2;     // 0,4,8,12

    // 64 batch rows x 16 k each iter: all 256 threads load one float4
    float4 ph  = *(const float4*)&hin[(b0 + lr) * Hh + lk];
    float4 pw0 = *(const float4*)&Wbase[(size_t)lr * Hh + lk];
    float4 pw1 = *(const float4*)&Wbase[(size_t)(lr + 64) * Hh + lk];

    for (int k0 = 0; k0 < Hh; k0 += 16) {
        __syncthreads();
        Hs[lk + 0][lr] = ph.x; Hs[lk + 1][lr] = ph.y;
        Hs[lk + 2][lr] = ph.z; Hs[lk + 3][lr] = ph.w;
        Ws[lk + 0][lr] = pw0.x; Ws[lk + 1][lr] = pw0.y;
        Ws[lk + 2][lr] = pw0.z; Ws[lk + 3][lr] = pw0.w;
        Ws[lk + 0][lr + 64] = pw1.x; Ws[lk + 1][lr + 64] = pw1.y;
        Ws[lk + 2][lr + 64] = pw1.z; Ws[lk + 3][lr + 64] = pw1.w;
        __syncthreads();
        int k1 = k0 + 16;
        if (k1 < Hh) {
            ph  = *(const float4*)&hin[(b0 + lr) * Hh + k1 + lk];
            pw0 = *(const float4*)&Wbase[(size_t)lr * Hh + k1 + lk];
            pw1 = *(const float4*)&Wbase[(size_t)(lr + 64) * Hh + k1 + lk];
        }
#pragma unroll
        for (int k = 0; k < 16; k++) {
            ull b2[2];
            const ull* bp2 = (const ull*)&Ws[k][tx << 2];
            b2[0] = bp2[0]; b2[1] = bp2[1];
#pragma unroll
            for (int i = 0; i < 8; i++) {
                float a = Hs[k][(ty << 3) + i];
                ull ad = pack2(a, a);
                acc[i][0] = ffma2(ad, b2[0], acc[i][0]);
                acc[i][1] = ffma2(ad, b2[1], acc[i][1]);
            }
        }
    }

    const int h = h0 + tx;
    const float4 b4 = *(const float4*)&bia[4 * h];
#pragma unroll
    for (int i = 0; i < 8; i++) {
        int b = b0 + (ty << 3) + i;
        float zi, zf_, zg, zo;
        unpack2(acc[i][0], zi, zf_);
        unpack2(acc[i][1], zg, zo);
        float4 pr = *(const float4*)&pre[((size_t)tc * Bq + b) * H4 + 4 * h];
        zi += pr.x + b4.x; zf_ += pr.y + b4.y;
        zg += pr.z + b4.z; zo += pr.w + b4.w;
        float c = cs[b * Hh + h];
        c = sigf(zf_) * c + sigf(zi) * tanhf(zg);
        float hn = sigf(zo) * tanhf(c);
        cs[b * Hh + h] = c;
        hout[b * Hh + h] = hn;
        out[((size_t)tc * Bq + b) * H2 + dir * Hh + h] = hn;
    }
}

// ---------------- zero LSTM states ------------------------------------------
__global__ void zero_states_kernel() {
    int i = blockIdx.x * blockDim.x + threadIdx.x;
    if (i < Bq * Hh) {
        g_hf2[0][i] = 0.0f; g_hf2[1][i] = 0.0f;
        g_hb2[0][i] = 0.0f; g_hb2[1][i] = 0.0f;
        g_cf[i] = 0.0f; g_cb[i] = 0.0f;
    }
}

// ---------------- alphas: [tb][r] = dot(hbar[tb], ws2[r]) -------------------
__global__ void alphas_kernel(const float* __restrict__ hbar,
                              const float* __restrict__ ws2,
                              float* __restrict__ alph) {
    __shared__ float w[Rr * 353];
    int tid = threadIdx.x;  // 128
    for (int i = tid; i < Rr * DAa; i += 128) {
        int r = i / DAa, k = i - r * DAa;
        w[r * 353 + k] = ws2[i];
    }
    __syncthreads();
    int row = blockIdx.x * 8 + (tid >> 4);
    int r = tid & 15;
    const float* hb = hbar + (size_t)row * DAa;
    float acc = 0.0f;
    for (int k = 0; k < DAa; k++) acc += hb[k] * w[r * 353 + k];
    alph[(size_t)row * Rr + r] = acc;
}

// ---------------- sent: sent[b,r,e] = sum_t alphas[t,b,r] * l1[t,b,e] -------
__global__ void sent_kernel(const float* __restrict__ alphas,
                            const float* __restrict__ l1,
                            float* __restrict__ outSent) {
    int b = blockIdx.x;
    __shared__ float al[Tt * Rr];
    int tid = threadIdx.x;
    for (int i = tid; i < Tt * Rr; i += 256) {
        int t = i / Rr, r = i % Rr;
        al[i] = alphas[(size_t)(t * Bq + b) * Rr + r];
    }
    __syncthreads();
    for (int e = tid; e < H2; e += 256) {
        float acc[Rr];
#pragma unroll
        for (int r = 0; r < Rr; r++) acc[r] = 0.0f;
        for (int t = 0; t < Tt; t++) {
            float v = l1[(size_t)(t * Bq + b) * H2 + e];
#pragma unroll
            for (int r = 0; r < Rr; r++) acc[r] += al[t * Rr + r] * v;
        }
#pragma unroll
        for (int r = 0; r < Rr; r++)
            outSent[(size_t)(b * Rr + r) * H2 + e] = acc[r];
    }
}

// ---------------- votes: per-r NN GEMM, M=256, N=1024, K=1024 ---------------
__global__ void votes_gemm(const float* __restrict__ sent,
                           const float* __restrict__ capsW,
                           float* __restrict__ votes) {
    int rr = blockIdx.z;
    const float* Bp = capsW + (size_t)rr * H2 * (Ss * Aa);
    __shared__ float As[16][64];
    __shared__ float Bs[16][65];
    int m0 = blockIdx.y * 64, n0 = blockIdx.x * 64;
    int tid = threadIdx.y * 16 + threadIdx.x;
    float acc[4][4] = {};
    for (int k0 = 0; k0 < H2; k0 += 16) {
#pragma unroll
        for (int q = 0; q < 4; q++) {
            int e = tid + q * 256;
            int r = e >> 4, c = e & 15;
            As[c][r] = sent[((size_t)(m0 + r) * Rr + rr) * H2 + k0 + c];
            int kr = e >> 6, nc = e & 63;
            Bs[kr][nc] = Bp[(size_t)(k0 + kr) * (Ss * Aa) + n0 + nc];
        }
        __syncthreads();
#pragma unroll
        for (int k = 0; k < 16; k++) {
            float a[4], w[4];
#pragma unroll
            for (int i = 0; i < 4; i++) a[i] = As[k][threadIdx.y * 4 + i];
#pragma unroll
            for (int j = 0; j < 4; j++) w[j] = Bs[k][threadIdx.x * 4 + j];
#pragma unroll
            for (int i = 0; i < 4; i++)
#pragma unroll
                for (int j = 0; j < 4; j++) acc[i][j] += a[i] * w[j];
        }
        __syncthreads();
    }
#pragma unroll
    for (int i = 0; i < 4; i++)
#pragma unroll
        for (int j = 0; j < 4; j++) {
            int mm = m0 + threadIdx.y * 4 + i;
            int nn = n0 + threadIdx.x * 4 + j;
            votes[((size_t)mm * Rr + rr) * (Ss * Aa) + nn] = acc[i][j];
        }
}

// ---------------- dynamic routing (NR=3) + class logits ---------------------
__global__ void routing_kernel(const float* __restrict__ votes,
                               float* __restrict__ outCls) {
    int b = blockIdx.x, tid = threadIdx.x;
    __shared__ float logits[Rr * Ss];
    __shared__ float route[Rr * Ss];
    __shared__ float pre[Ss * Aa];
    __shared__ float scale[Ss];
    for (int i = tid; i < Rr * Ss; i += 256) logits[i] = 0.0f;
    const float* vb = votes + (size_t)b * Rr * Ss * Aa;
    for (int it = 0; it < NRr; it++) {
        __syncthreads();
        if (tid < Rr) {
            float mx = -1e30f;
            for (int s = 0; s < Ss; s++) mx = fmaxf(mx, logits[tid * Ss + s]);
            float sum = 0.0f;
            for (int s = 0; s < Ss; s++) {
                float e = expf(logits[tid * Ss + s] - mx);
                route[tid * Ss + s] = e;
                sum += e;
            }
            float inv = 1.0f / sum;
            for (int s = 0; s < Ss; s++) route[tid * Ss + s] *= inv;
        }
        __syncthreads();
        for (int i = tid; i < Ss * Aa; i += 256) {
            int s = i / Aa, a = i % Aa;
            float acc = 0.0f;
            for (int r = 0; r < Rr; r++)
                acc += route[r * Ss + s] * vb[(r * Ss + s) * Aa + a];
            pre[i] = acc;
        }
        __syncthreads();
        if (tid < Ss) {
            float n2 = 0.0f;
            for (int a = 0; a < Aa; a++) n2 += pre[tid * Aa + a] * pre[tid * Aa + a];
            float n = sqrtf(n2);
            scale[tid] = n / (0.5f + n2);
            if (it == NRr - 1) outCls[b * Ss + tid] = n2 / (0.5f + n2);
        }
        __syncthreads();
        if (it < NRr - 1) {
            for (int i = tid; i < Rr * Ss; i += 256) {
                int r = i / Ss, s = i % Ss;
                float acc = 0.0f;
                float sc = scale[s];
                for (int a = 0; a < Aa; a++)
                    acc += vb[(r * Ss + s) * Aa + a] * pre[s * Aa + a] * sc;
                logits[i] += acc;
            }
        }
    }
}

// ---------------- host launch ------------------------------------------------
static float* symf(const void* s) {
    void* p = nullptr;
    cudaGetSymbolAddress(&p, s);
    return (float*)p;
}

extern "C" void kernel_launch(void* const* d_in, const int* in_sizes, int n_in,
                              void* d_out, int out_size) {
    const int*   tokens  = (const int*)d_in[0];
    const float* emb     = (const float*)d_in[2];
    const float* Wih_l0f = (const float*)d_in[3];
    const float* Whh_l0f = (const float*)d_in[4];
    const float* b_l0f   = (const float*)d_in[5];
    const float* Wih_l0b = (const float*)d_in[6];
    const float* Whh_l0b = (const float*)d_in[7];
    const float* b_l0b   = (const float*)d_in[8];
    const float* Wih_l1f = (const float*)d_in[9];
    const float* Whh_l1f = (const float*)d_in[10];
    const float* b_l1f   = (const float*)d_in[11];
    const float* Wih_l1b = (const float*)d_in[12];
    const float* Whh_l1b = (const float*)d_in[13];
    const float* b_l1b   = (const float*)d_in[14];
    const float* ws1     = (const float*)d_in[15];
    const float* ws2     = (const float*)d_in[16];
    const float* capsW   = (const float*)d_in[17];
    float* out = (float*)d_out;

    float* x     = symf(g_x);
    float* pre_f = symf(g_pre_f);
    float* pre_b = symf(g_pre_b);
    float* l0    = symf(g_l0);
    float* l1    = symf(g_l1);
    float* hbar  = symf(g_hbar);
    float* alph  = symf(g_alphas);
    float* votes = symf(g_votes);
    float* wih0f = symf(g_wih0f); float* wih0b = symf(g_wih0b);
    float* wih1f = symf(g_wih1f); float* wih1b = symf(g_wih1b);
    float* whh0f = symf(g_whh0f); float* whh0b = symf(g_whh0b);
    float* whh1f = symf(g_whh1f); float* whh1b = symf(g_whh1b);
    float* bp0f  = symf(g_b0f);   float* bp0b  = symf(g_b0b);
    float* bp1f  = symf(g_b1f);   float* bp1b  = symf(g_b1b);
    // base symbols only; offset in host pointer arithmetic (NOT symbol+offset)
    float* hfbase = symf(g_hf2);
    float* hbbase = symf(g_hb2);
    float* hf0 = hfbase;              float* hf1 = hfbase + Bq * Hh;
    float* hb0 = hbbase;              float* hb1 = hbbase + Bq * Hh;

    const int MB = Tt * Bq;  // 16384

    // 1. embedding (padded) + weight repacks
    embed_kernel<<<4096, 256>>>(tokens, emb);
    pack_w<<<1024, 256>>>(Wih_l0f, wih0f, Ee, EeP);
    pack_w<<<1024, 256>>>(Wih_l0b, wih0b, Ee, EeP);
    pack_w<<<2048, 256>>>(Wih_l1f, wih1f, H2, H2);
    pack_w<<<2048, 256>>>(Wih_l1b, wih1b, H2, H2);
    pack_w<<<1024, 256>>>(Whh_l0f, whh0f, Hh, Hh);
    pack_w<<<1024, 256>>>(Whh_l0b, whh0b, Hh, Hh);
    pack_w<<<1024, 256>>>(Whh_l1f, whh1f, Hh, Hh);
    pack_w<<<1024, 256>>>(Whh_l1b, whh1b, Hh, Hh);
    pack_bias<<<8, 256>>>(b_l0f, bp0f);
    pack_bias<<<8, 256>>>(b_l0b, bp0b);
    pack_bias<<<8, 256>>>(b_l1f, bp1f);
    pack_bias<<<8, 256>>>(b_l1b, bp1b);

    dim3 gP(H4 / 128, MB / 128);  // projections: 16 x 128
    dim3 gR(Hh / 32, Bq / 64, 2); // recurrence: 16 x 4 x 2

    // 2. layer0 input projections (permuted cols)
    gemm128<<<gP, 256>>>(x, wih0f, pre_f, MB, H4, EeP, 0);
    gemm128<<<gP, 256>>>(x, wih0b, pre_b, MB, H4, EeP, 0);

    // 3. layer0 recurrence (h ping-pong)
    zero_states_kernel<<<(Bq * Hh + 255) / 256, 256>>>();
    for (int t = 0; t < Tt; t++) {
        float* hinf = (t & 1) ? hf1 : hf0;  float* houtf = (t & 1) ? hf0 : hf1;
        float* hinb = (t & 1) ? hb1 : hb0;  float* houtb = (t & 1) ? hb0 : hb1;
        recur_fused<<<gR, 256>>>(t, whh0f, whh0b, bp0f, bp0b, pre_f, pre_b,
                                 hinf, hinb, houtf, houtb, l0);
    }

    // 4. layer1 input projections
    gemm128<<<gP, 256>>>(l0, wih1f, pre_f, MB, H4, H2, 0);
    gemm128<<<gP, 256>>>(l0, wih1b, pre_b, MB, H4, H2, 0);

    // 5. layer1 recurrence
    zero_states_kernel<<<(Bq * Hh + 255) / 256, 256>>>();
    for (int t = 0; t < Tt; t++) {
        float* hinf = (t & 1) ? hf1 : hf0;  float* houtf = (t & 1) ? hf0 : hf1;
        float* hinb = (t & 1) ? hb1 : hb0;  float* houtb = (t & 1) ? hb0 : hb1;
        recur_fused<<<gR, 256>>>(t, whh1f, whh1b, bp1f, bp1b, pre_f, pre_b,
                                 hinf, hinb, houtf, houtb, l1);
    }

    // 6. attention: hbar = tanh(l1 @ ws1^T), alphas = hbar @ ws2^T
    gemm128<<<dim3((DAa + 127) / 128, MB / 128), 256>>>(l1, ws1, hbar, MB, DAa, H2, 1);
    alphas_kernel<<<MB / 8, 128>>>(hbar, ws2, alph);

    // 7. sent -> d_out[0 : B*R*2H)
    sent_kernel<<<Bq, 256>>>(alph, l1, out);

    // 8. votes
    votes_gemm<<<dim3((Ss * Aa) / 64, Bq / 64, Rr), dim3(16, 16)>>>(out, capsW, votes);

    // 9. routing -> class logits
    routing_kernel<<<Bq, 256>>>(votes, out + (size_t)Bq * Rr * H2);
}